// round 16
// baseline (speedup 1.0000x reference)
#include <cuda_runtime.h>
#include <cuda_fp16.h>
#include <math.h>
#include <stdint.h>

// ---------------------------------------------------------------------------
// Problem constants
// ---------------------------------------------------------------------------
#define BB   16
#define SS   1024
#define EE   1024
#define HH   16
#define HD   64
#define FFN  4096
#define MM   (BB * SS)          // 16384 rows

// ---------------------------------------------------------------------------
// Scratch buffers (device globals: allocation-free, graph-capture safe)
// ---------------------------------------------------------------------------
__device__ __align__(16) __half g_h   [(size_t)MM * EE];
__device__ __align__(16) __half g_qkv [(size_t)MM * 3 * EE];
__device__ __align__(16) __half g_attn[(size_t)MM * EE];
__device__ __align__(16) float  g_x2  [(size_t)MM * EE];
__device__ __align__(16) __half g_ffn [(size_t)MM * FFN];
// pre-cast fp16 weights
__device__ __align__(16) __half g_wq  [(size_t)3 * EE * EE];
__device__ __align__(16) __half g_wo  [(size_t)EE * EE];
__device__ __align__(16) __half g_w1  [(size_t)FFN * EE];
__device__ __align__(16) __half g_w2  [(size_t)EE * FFN];

// ---------------------------------------------------------------------------
// PTX helpers (sm_100 plain target: cp.async + mma.sync + ldmatrix)
// ---------------------------------------------------------------------------
__device__ __forceinline__ uint32_t smem_u32(const void* p) {
    uint32_t a;
    asm("{ .reg .u64 t; cvta.to.shared.u64 t, %1; cvt.u32.u64 %0, t; }"
        : "=r"(a) : "l"(p));
    return a;
}

__device__ __forceinline__ void cp_async16(uint32_t dst, const void* src) {
    asm volatile("cp.async.cg.shared.global [%0], [%1], 16;"
                 :: "r"(dst), "l"(src) : "memory");
}
#define CP_COMMIT() asm volatile("cp.async.commit_group;" ::: "memory")
#define CP_WAIT(n)  asm volatile("cp.async.wait_group %0;" :: "n"(n) : "memory")

// fp16 m16n8k16 mma, fp32 accumulate
#define MMA_F16(c, a, b0v, b1v) \
    asm volatile("mma.sync.aligned.m16n8k16.row.col.f32.f16.f16.f32 " \
        "{%0,%1,%2,%3}, {%4,%5,%6,%7}, {%8,%9}, {%0,%1,%2,%3};" \
        : "+f"((c)[0]), "+f"((c)[1]), "+f"((c)[2]), "+f"((c)[3]) \
        : "r"((a)[0]), "r"((a)[1]), "r"((a)[2]), "r"((a)[3]), \
          "r"(b0v), "r"(b1v))

#define LDSM_X4(r, addr) \
    asm volatile("ldmatrix.sync.aligned.m8n8.x4.shared.b16 {%0,%1,%2,%3}, [%4];" \
        : "=r"((r)[0]), "=r"((r)[1]), "=r"((r)[2]), "=r"((r)[3]) : "r"(addr))
#define LDSM_X2(r, addr) \
    asm volatile("ldmatrix.sync.aligned.m8n8.x2.shared.b16 {%0,%1}, [%2];" \
        : "=r"((r)[0]), "=r"((r)[1]) : "r"(addr))
#define LDSM_X2T(r, addr) \
    asm volatile("ldmatrix.sync.aligned.m8n8.x2.trans.shared.b16 {%0,%1}, [%2];" \
        : "=r"((r)[0]), "=r"((r)[1]) : "r"(addr))

__device__ __forceinline__ uint32_t pack_h2(float lo, float hi) {
    __half2 h = __floats2half2_rn(lo, hi);
    return *(uint32_t*)&h;
}

// ---------------------------------------------------------------------------
// Weight pre-cast: fp32 -> fp16
// ---------------------------------------------------------------------------
__global__ __launch_bounds__(256)
void half_cast(const float* __restrict__ s, __half* __restrict__ d, int n4)
{
    const int i = blockIdx.x * 256 + threadIdx.x;
    if (i < n4) {
        const float4 v = ((const float4*)s)[i];
        uint2 o;
        o.x = pack_h2(v.x, v.y);
        o.y = pack_h2(v.z, v.w);
        ((uint2*)d)[i] = o;
    }
}

// ---------------------------------------------------------------------------
// fp16 mma.sync GEMM: C[M,N] = A[M,K] @ W[N,K]^T + bias (+gelu / +residual)
//   128x128 CTA tile, 4 warps (2x2), warp tile 64x64 -> 32 MMA per 8 LDSM.x4.
//   BK=64 (rows = 128B, verified XOR swizzle), 3-stage cp.async,
//   single sync per k-iter. Accumulation order identical to R14 (bitwise).
// ---------------------------------------------------------------------------
#define EPI_NONE 0
#define EPI_GELU 1
#define EPI_RES  2

#define GBK       64
#define GSTAGES   3
#define ABLK_B    (128 * 128)                 // 16384 bytes (128 rows x 128B)
#define STAGE_B   (2 * ABLK_B)                // 32768
#define DSMEM_SZ  (GSTAGES * STAGE_B)         // 98304 bytes

template<int EPI, bool OH>
__global__ __launch_bounds__(128, 2)
void gemm_mma(const __half* __restrict__ A, const __half* __restrict__ W,
              const float* __restrict__ bias, const float* __restrict__ Res,
              void* __restrict__ Cv, int N, int K)
{
    extern __shared__ char smc[];
    const uint32_t smA = smem_u32(smc);

    const int tid  = threadIdx.x;
    const int bm   = blockIdx.y * 128;
    const int bn   = blockIdx.x * 128;
    const int warp = tid >> 5, lane = tid & 31;
    const int wm   = (warp >> 1) * 64;        // 0,64
    const int wn   = (warp & 1) * 64;         // 0,64
    const int qr   = lane >> 2;               // 0..7
    const int qc   = lane & 3;                // 0..3
    const int lx   = lane & 7;

    // ldmatrix bases (bytes, stage-relative); rows are 128B
    const uint32_t aRow = (uint32_t)(wm + (lane & 15)) << 7;
    const uint32_t aBit = (uint32_t)(lane >> 4);
    // B x4: lanes 0-15 -> first n8-tile rows, lanes 16-31 -> +8 rows
    const uint32_t bRow = (uint32_t)(wn + ((lane >> 4) << 3) + lx) << 7;
    const uint32_t bBit = (uint32_t)((lane >> 3) & 1);

    float acc[4][8][4];
    #pragma unroll
    for (int i = 0; i < 4; i++)
        #pragma unroll
        for (int j = 0; j < 8; j++)
            #pragma unroll
            for (int k = 0; k < 4; k++) acc[i][j][k] = 0.f;

    // cp.async: thread -> one full 128B row of A and of B per stage
    const __half* Ap = A + (long)(bm + tid) * K;
    const __half* Wp = W + (long)(bn + tid) * K;
    const uint32_t dA = smA + tid * 128;
    const uint32_t dB = smA + ABLK_B + tid * 128;
    const int rx = tid & 7;

    const int T = K / GBK;

    // prologue: stages 0,1
    #pragma unroll
    for (int u = 0; u < 2; ++u) {
        const uint32_t sb = u * STAGE_B;
        #pragma unroll
        for (int c = 0; c < 8; c++) {
            const uint32_t so = ((c ^ rx) << 4);
            cp_async16(dA + sb + so, Ap + (long)u * GBK + c * 8);
            cp_async16(dB + sb + so, Wp + (long)u * GBK + c * 8);
        }
        CP_COMMIT();
    }

    for (int t = 0; t < T; ++t) {
        CP_WAIT(1);
        __syncthreads();

        if (t + 2 < T) {
            const int u = t + 2;
            const uint32_t sb = (u % GSTAGES) * STAGE_B;
            #pragma unroll
            for (int c = 0; c < 8; c++) {
                const uint32_t so = ((c ^ rx) << 4);
                cp_async16(dA + sb + so, Ap + (long)u * GBK + c * 8);
                cp_async16(dB + sb + so, Wp + (long)u * GBK + c * 8);
            }
        }
        CP_COMMIT();

        const uint32_t stb = smA + (t % GSTAGES) * STAGE_B;

        #pragma unroll
        for (int ks = 0; ks < 4; ++ks) {      // 4 x k16 = 64 K per iter
            uint32_t a[4][4], b4[4][4];
            const uint32_t aAddr = stb + aRow
                                 + ((((uint32_t)(ks << 1) + aBit) ^ ((aRow >> 7) & 7u)) << 4);
            const uint32_t bAddr = stb + ABLK_B + bRow
                                 + ((((uint32_t)(ks << 1) + bBit) ^ ((bRow >> 7) & 7u)) << 4);
            #pragma unroll
            for (int mt = 0; mt < 4; ++mt)
                LDSM_X4(a[mt], aAddr + mt * 2048);
            #pragma unroll
            for (int nt2 = 0; nt2 < 4; ++nt2)
                LDSM_X4(b4[nt2], bAddr + nt2 * 2048);   // 16 rows = 2048B
            #pragma unroll
            for (int mt = 0; mt < 4; ++mt)
                #pragma unroll
                for (int nt = 0; nt < 8; ++nt)
                    MMA_F16(acc[mt][nt], a[mt],
                            b4[nt >> 1][(nt & 1) * 2],
                            b4[nt >> 1][(nt & 1) * 2 + 1]);
        }
    }

    // epilogue (acc fp32; OH -> fp16 output, else fp32)
    #pragma unroll
    for (int mt = 0; mt < 4; ++mt) {
        #pragma unroll
        for (int r2 = 0; r2 < 2; ++r2) {
            const long row = bm + wm + mt * 16 + qr + r2 * 8;
            const float* Rrow = (EPI == EPI_RES) ? (Res + row * (long)N + bn)
                                                 : (const float*)nullptr;
            #pragma unroll
            for (int nt = 0; nt < 8; ++nt) {
                const int col = wn + nt * 8 + qc * 2;
                float vx = acc[mt][nt][r2 * 2 + 0];
                float vy = acc[mt][nt][r2 * 2 + 1];
                const float2 bv = *(const float2*)(bias + bn + col);
                vx += bv.x; vy += bv.y;
                if (EPI == EPI_GELU) {
                    vx = 0.5f * vx * (1.0f + erff(vx * 0.7071067811865475f));
                    vy = 0.5f * vy * (1.0f + erff(vy * 0.7071067811865475f));
                }
                if (EPI == EPI_RES) {
                    const float2 rv = *(const float2*)(Rrow + col);
                    vx += rv.x; vy += rv.y;
                }
                if (OH) {
                    __half* Crow = (__half*)Cv + row * (long)N + bn;
                    *(uint32_t*)(Crow + col) = pack_h2(vx, vy);
                } else {
                    float* Crow = (float*)Cv + row * (long)N + bn;
                    float2 o; o.x = vx; o.y = vy;
                    *(float2*)(Crow + col) = o;
                }
            }
        }
    }
}

// ---------------------------------------------------------------------------
// LayerNorm: fp32 in, fp16 out (consumed only as GEMM A operand)
// ---------------------------------------------------------------------------
__global__ __launch_bounds__(256)
void ln_kernel(const float* __restrict__ x, const float* __restrict__ w,
               const float* __restrict__ b, __half* __restrict__ y)
{
    const long row = blockIdx.x;
    const float4* xr = (const float4*)(x + (row << 10));
    float4 xv = xr[threadIdx.x];

    float s  = xv.x + xv.y + xv.z + xv.w;
    float sq = xv.x * xv.x + xv.y * xv.y + xv.z * xv.z + xv.w * xv.w;
    #pragma unroll
    for (int o = 16; o; o >>= 1) {
        s  += __shfl_xor_sync(0xffffffffu, s,  o);
        sq += __shfl_xor_sync(0xffffffffu, sq, o);
    }
    __shared__ float ss[8], ssq[8];
    __shared__ float mu_s, rstd_s;
    const int warp = threadIdx.x >> 5, lane = threadIdx.x & 31;
    if (lane == 0) { ss[warp] = s; ssq[warp] = sq; }
    __syncthreads();
    if (threadIdx.x == 0) {
        float S = 0.f, SQ = 0.f;
        #pragma unroll
        for (int i = 0; i < 8; i++) { S += ss[i]; SQ += ssq[i]; }
        const float mu  = S * (1.0f / 1024.0f);
        const float var = SQ * (1.0f / 1024.0f) - mu * mu;
        mu_s   = mu;
        rstd_s = rsqrtf(var + 1e-6f);
    }
    __syncthreads();
    const float mu = mu_s, rstd = rstd_s;

    const float4 wv = ((const float4*)w)[threadIdx.x];
    const float4 bv = ((const float4*)b)[threadIdx.x];
    uint2 o;
    o.x = pack_h2((xv.x - mu) * rstd * wv.x + bv.x,
                  (xv.y - mu) * rstd * wv.y + bv.y);
    o.y = pack_h2((xv.z - mu) * rstd * wv.z + bv.z,
                  (xv.w - mu) * rstd * wv.w + bv.w);
    ((uint2*)(y + (row << 10)))[threadIdx.x] = o;
}

// ---------------------------------------------------------------------------
// Flash attention, fp16 mma.sync m16n8k16 (unchanged from R14).
// ---------------------------------------------------------------------------
#define QROWS   128
#define AQ_B    144
#define AK_B    144
#define AV_B    144
#define AP_B    80
#define OFF_Q   0
#define OFF_K   (QROWS * AQ_B)                         // 18432
#define OFF_V   (OFF_K + 2 * 32 * AK_B)                // 27648
#define OFF_P   (OFF_V + 2 * 32 * AV_B)                // 36864
#define ATTN_SMEM (OFF_P + QROWS * AP_B)               // 47104 B

__global__ __launch_bounds__(256, 2)
void attn_mma(const __half* __restrict__ qkv, __half* __restrict__ out)
{
    extern __shared__ char asmc[];
    const uint32_t smb = smem_u32(asmc);
    const uint32_t sQ = smb + OFF_Q, sK = smb + OFF_K;
    const uint32_t sV = smb + OFF_V, sP = smb + OFF_P;

    const int tid  = threadIdx.x;
    const int warp = tid >> 5, lane = tid & 31;
    const int qr   = lane >> 2, qc = lane & 3;
    const int lx   = lane & 7;
    const int b    = blockIdx.y >> 4, h = blockIdx.y & 15;
    const int q0   = blockIdx.x * QROWS;
    const int wm   = warp * 16;               // 0..112
    const long base = (long)b * SS * 3072 + h * 64;

    // Q tile (128 rows x 8 chunks = 1024): 4 per thread
    #pragma unroll
    for (int i = 0; i < 4; i++) {
        const int cc = tid + i * 256;
        const int row = cc >> 3, c = cc & 7;
        cp_async16(sQ + row * AQ_B + c * 16,
                   qkv + base + (long)(q0 + row) * 3072 + c * 8);
    }
    // K/V tile kt=0 (32 rows x 8 chunks = 256 each): 1 per thread each
    {
        const int row = tid >> 3, c = tid & 7;
        const long ko = base + 1024 + (long)row * 3072 + c * 8;
        cp_async16(sK + row * AK_B + c * 16, qkv + ko);
        cp_async16(sV + row * AV_B + c * 16, qkv + ko + 1024);
    }
    CP_COMMIT();
    CP_WAIT(0);
    __syncthreads();

    // Q fragments: scale by 0.125 (exact in fp16), register-resident.
    uint32_t qa[4][4];
    {
        const int r0off = OFF_Q + (wm + qr) * AQ_B + qc * 4;
        const int r1off = r0off + 8 * AQ_B;
        const __half2 s8 = __floats2half2_rn(0.125f, 0.125f);
        #pragma unroll
        for (int ks = 0; ks < 4; ks++) {
            __half2 a0 = __hmul2(*(const __half2*)(asmc + r0off + ks * 32), s8);
            __half2 a1 = __hmul2(*(const __half2*)(asmc + r1off + ks * 32), s8);
            __half2 a2 = __hmul2(*(const __half2*)(asmc + r0off + ks * 32 + 16), s8);
            __half2 a3 = __hmul2(*(const __half2*)(asmc + r1off + ks * 32 + 16), s8);
            qa[ks][0] = *(uint32_t*)&a0;
            qa[ks][1] = *(uint32_t*)&a1;
            qa[ks][2] = *(uint32_t*)&a2;
            qa[ks][3] = *(uint32_t*)&a3;
        }
    }

    const uint32_t kBit = (uint32_t)((lane >> 3) & 1);

    float o[8][4];
    #pragma unroll
    for (int nt = 0; nt < 8; nt++)
        #pragma unroll
        for (int k = 0; k < 4; k++) o[nt][k] = 0.f;
    float mrow0 = -1e30f, mrow1 = -1e30f, l0 = 0.f, l1 = 0.f;

    for (int kt = 0; kt < 32; kt++) {
        const int cur = kt & 1;
        CP_WAIT(0);
        __syncthreads();
        if (kt + 1 < 32) {
            const int nxt = cur ^ 1;
            const int row = tid >> 3, c = tid & 7;
            const long ko = base + 1024
                          + (long)((kt + 1) * 32 + row) * 3072 + c * 8;
            cp_async16(sK + (nxt * 32 + row) * AK_B + c * 16, qkv + ko);
            cp_async16(sV + (nxt * 32 + row) * AV_B + c * 16, qkv + ko + 1024);
        }
        CP_COMMIT();

        const uint32_t sKc = sK + cur * 32 * AK_B;
        const uint32_t sVc = sV + cur * 32 * AV_B;

        // S = (Q/8) K^T : 4 k16-steps, K frags LDSM.x2
        float s[4][4];
        #pragma unroll
        for (int nt = 0; nt < 4; nt++)
            #pragma unroll
            for (int k = 0; k < 4; k++) s[nt][k] = 0.f;
        #pragma unroll
        for (int ks = 0; ks < 4; ks++) {
            const uint32_t kAddr = sKc + (uint32_t)lx * AK_B
                                 + (((uint32_t)(ks << 1) + kBit) << 4);
            uint32_t bf[4][2];
            #pragma unroll
            for (int nt = 0; nt < 4; nt++)
                LDSM_X2(bf[nt], kAddr + nt * (8 * AK_B));
            #pragma unroll
            for (int nt = 0; nt < 4; nt++)
                MMA_F16(s[nt], qa[ks], bf[nt][0], bf[nt][1]);
        }

        // online softmax
        float m0 = -1e30f, m1 = -1e30f;
        #pragma unroll
        for (int nt = 0; nt < 4; nt++) {
            m0 = fmaxf(m0, fmaxf(s[nt][0], s[nt][1]));
            m1 = fmaxf(m1, fmaxf(s[nt][2], s[nt][3]));
        }
        m0 = fmaxf(m0, __shfl_xor_sync(0xffffffffu, m0, 1));
        m0 = fmaxf(m0, __shfl_xor_sync(0xffffffffu, m0, 2));
        m1 = fmaxf(m1, __shfl_xor_sync(0xffffffffu, m1, 1));
        m1 = fmaxf(m1, __shfl_xor_sync(0xffffffffu, m1, 2));
        const float n0 = fmaxf(mrow0, m0), n1 = fmaxf(mrow1, m1);
        const float c0 = __expf(mrow0 - n0), c1 = __expf(mrow1 - n1);
        float ps0 = 0.f, ps1 = 0.f;
        char* P0 = asmc + (OFF_P + (wm + qr) * AP_B + qc * 4);
        char* P1 = P0 + 8 * AP_B;
        #pragma unroll
        for (int nt = 0; nt < 4; nt++) {
            const float p00 = __expf(s[nt][0] - n0);
            const float p01 = __expf(s[nt][1] - n0);
            const float p10 = __expf(s[nt][2] - n1);
            const float p11 = __expf(s[nt][3] - n1);
            ps0 += p00 + p01;
            ps1 += p10 + p11;
            *(uint32_t*)(P0 + nt * 16) = pack_h2(p00, p01);
            *(uint32_t*)(P1 + nt * 16) = pack_h2(p10, p11);
        }
        ps0 += __shfl_xor_sync(0xffffffffu, ps0, 1);
        ps0 += __shfl_xor_sync(0xffffffffu, ps0, 2);
        ps1 += __shfl_xor_sync(0xffffffffu, ps1, 1);
        ps1 += __shfl_xor_sync(0xffffffffu, ps1, 2);
        l0 = l0 * c0 + ps0;
        l1 = l1 * c1 + ps1;
        mrow0 = n0; mrow1 = n1;
        #pragma unroll
        for (int nt = 0; nt < 8; nt++) {
            o[nt][0] *= c0; o[nt][1] *= c0;
            o[nt][2] *= c1; o[nt][3] *= c1;
        }
        __syncwarp();

        // O += P V : 2 k16-steps; P LDSM.x4, V LDSM.x2.trans
        #pragma unroll
        for (int ks2 = 0; ks2 < 2; ks2++) {
            uint32_t pa[4];
            const uint32_t pAddr = sP + (uint32_t)(wm + (lane & 15)) * AP_B
                                 + (((uint32_t)(ks2 << 1) + (uint32_t)(lane >> 4)) << 4);
            LDSM_X4(pa, pAddr);
            const uint32_t vRow = sVc
                + (uint32_t)(ks2 * 16 + (lane & 7) + ((lane >> 3) & 1) * 8) * AV_B;
            #pragma unroll
            for (int nt = 0; nt < 8; nt++) {
                uint32_t bv[2];
                LDSM_X2T(bv, vRow + (nt << 4));
                MMA_F16(o[nt], pa, bv[0], bv[1]);
            }
        }
        __syncwarp();
    }

    const float i0 = 1.0f / l0, i1 = 1.0f / l1;
    const long r0g = (long)(b * SS + q0 + wm + qr);
    __half* d0 = out + r0g * EE + h * 64 + 2 * qc;
    __half* d1 = d0 + 8 * EE;
    #pragma unroll
    for (int nt = 0; nt < 8; nt++) {
        *(uint32_t*)(d0 + nt * 8) = pack_h2(o[nt][0] * i0, o[nt][1] * i0);
        *(uint32_t*)(d1 + nt * 8) = pack_h2(o[nt][2] * i1, o[nt][3] * i1);
    }
}

// ---------------------------------------------------------------------------
// Launch sequence
// ---------------------------------------------------------------------------
extern "C" void kernel_launch(void* const* d_in, const int* in_sizes, int n_in,
                              void* d_out, int out_size)
{
    const float* x         = (const float*)d_in[0];
    const float* ln1_w     = (const float*)d_in[1];
    const float* ln1_b     = (const float*)d_in[2];
    const float* ln2_w     = (const float*)d_in[3];
    const float* ln2_b     = (const float*)d_in[4];
    const float* in_proj_w = (const float*)d_in[5];
    const float* in_proj_b = (const float*)d_in[6];
    const float* out_w     = (const float*)d_in[7];
    const float* out_b     = (const float*)d_in[8];
    const float* w1        = (const float*)d_in[9];
    const float* b1        = (const float*)d_in[10];
    const float* w2        = (const float*)d_in[11];
    const float* b2        = (const float*)d_in[12];
    float* outp            = (float*)d_out;

    __half *h, *qkv, *attn, *ffn, *wq, *wo, *w1t, *w2t;
    float  *x2;
    cudaGetSymbolAddress((void**)&h,    g_h);
    cudaGetSymbolAddress((void**)&qkv,  g_qkv);
    cudaGetSymbolAddress((void**)&attn, g_attn);
    cudaGetSymbolAddress((void**)&x2,   g_x2);
    cudaGetSymbolAddress((void**)&ffn,  g_ffn);
    cudaGetSymbolAddress((void**)&wq,   g_wq);
    cudaGetSymbolAddress((void**)&wo,   g_wo);
    cudaGetSymbolAddress((void**)&w1t,  g_w1);
    cudaGetSymbolAddress((void**)&w2t,  g_w2);

    cudaFuncSetAttribute(gemm_mma<EPI_NONE, true>,  cudaFuncAttributeMaxDynamicSharedMemorySize, DSMEM_SZ);
    cudaFuncSetAttribute(gemm_mma<EPI_GELU, true>,  cudaFuncAttributeMaxDynamicSharedMemorySize, DSMEM_SZ);
    cudaFuncSetAttribute(gemm_mma<EPI_RES,  false>, cudaFuncAttributeMaxDynamicSharedMemorySize, DSMEM_SZ);
    cudaFuncSetAttribute(attn_mma, cudaFuncAttributeMaxDynamicSharedMemorySize, ATTN_SMEM);

    // 0. pre-cast weights to fp16 (HBM-bound, ~25us total)
    half_cast<<<(3 * EE * EE / 4 + 255) / 256, 256>>>(in_proj_w, wq, 3 * EE * EE / 4);
    half_cast<<<(EE * EE / 4 + 255) / 256, 256>>>(out_w, wo, EE * EE / 4);
    half_cast<<<(FFN * EE / 4 + 255) / 256, 256>>>(w1, w1t, FFN * EE / 4);
    half_cast<<<(EE * FFN / 4 + 255) / 256, 256>>>(w2, w2t, EE * FFN / 4);

    // 1. h = fp16(LN1(x))
    ln_kernel<<<MM, 256>>>(x, ln1_w, ln1_b, h);
    // 2. qkv = fp16(h @ wq^T + b)                     [16384, 3072]
    gemm_mma<EPI_NONE, true><<<dim3(3 * EE / 128, MM / 128), 128, DSMEM_SZ>>>(
        h, wq, in_proj_b, nullptr, qkv, 3 * EE, EE);
    // 3. attention (fp16 in/out, fp32 softmax+acc)
    attn_mma<<<dim3(SS / QROWS, BB * HH), 256, ATTN_SMEM>>>(qkv, attn);
    // 4. x2 = x + attn @ wo^T + out_b                 (fp32 out)
    gemm_mma<EPI_RES, false><<<dim3(EE / 128, MM / 128), 128, DSMEM_SZ>>>(
        attn, wo, out_b, x, x2, EE, EE);
    // 5. h = fp16(LN2(x2))
    ln_kernel<<<MM, 256>>>(x2, ln2_w, ln2_b, h);
    // 6. ffn = fp16(gelu(h @ w1^T + b1))              [16384, 4096]
    gemm_mma<EPI_GELU, true><<<dim3(FFN / 128, MM / 128), 128, DSMEM_SZ>>>(
        h, w1t, b1, nullptr, ffn, FFN, EE);
    // 7. out = x2 + ffn @ w2^T + b2                   (fp32 out)
    gemm_mma<EPI_RES, false><<<dim3(EE / 128, MM / 128), 128, DSMEM_SZ>>>(
        ffn, w2t, b2, x2, outp, EE, FFN);
}

// round 17
// speedup vs baseline: 1.3621x; 1.3621x over previous
#include <cuda_runtime.h>
#include <cuda_fp16.h>
#include <math.h>
#include <stdint.h>

// ---------------------------------------------------------------------------
// Problem constants
// ---------------------------------------------------------------------------
#define BB   16
#define SS   1024
#define EE   1024
#define HH   16
#define HD   64
#define FFN  4096
#define MM   (BB * SS)          // 16384 rows

// ---------------------------------------------------------------------------
// Scratch buffers (device globals: allocation-free, graph-capture safe)
// ---------------------------------------------------------------------------
__device__ __align__(16) __half g_h   [(size_t)MM * EE];
__device__ __align__(16) __half g_qkv [(size_t)MM * 3 * EE];
__device__ __align__(16) __half g_attn[(size_t)MM * EE];
__device__ __align__(16) float  g_x2  [(size_t)MM * EE];
__device__ __align__(16) __half g_ffn [(size_t)MM * FFN];
// pre-cast fp16 weights
__device__ __align__(16) __half g_wq  [(size_t)3 * EE * EE];
__device__ __align__(16) __half g_wo  [(size_t)EE * EE];
__device__ __align__(16) __half g_w1  [(size_t)FFN * EE];
__device__ __align__(16) __half g_w2  [(size_t)EE * FFN];

// ---------------------------------------------------------------------------
// PTX helpers (sm_100 plain target: cp.async + mma.sync + ldmatrix)
// ---------------------------------------------------------------------------
__device__ __forceinline__ uint32_t smem_u32(const void* p) {
    uint32_t a;
    asm("{ .reg .u64 t; cvta.to.shared.u64 t, %1; cvt.u32.u64 %0, t; }"
        : "=r"(a) : "l"(p));
    return a;
}

__device__ __forceinline__ void cp_async16(uint32_t dst, const void* src) {
    asm volatile("cp.async.cg.shared.global [%0], [%1], 16;"
                 :: "r"(dst), "l"(src) : "memory");
}
#define CP_COMMIT() asm volatile("cp.async.commit_group;" ::: "memory")
#define CP_WAIT(n)  asm volatile("cp.async.wait_group %0;" :: "n"(n) : "memory")

// fp16 m16n8k16 mma, fp32 accumulate
#define MMA_F16(c, a, b0v, b1v) \
    asm volatile("mma.sync.aligned.m16n8k16.row.col.f32.f16.f16.f32 " \
        "{%0,%1,%2,%3}, {%4,%5,%6,%7}, {%8,%9}, {%0,%1,%2,%3};" \
        : "+f"((c)[0]), "+f"((c)[1]), "+f"((c)[2]), "+f"((c)[3]) \
        : "r"((a)[0]), "r"((a)[1]), "r"((a)[2]), "r"((a)[3]), \
          "r"(b0v), "r"(b1v))

#define LDSM_X4(r, addr) \
    asm volatile("ldmatrix.sync.aligned.m8n8.x4.shared.b16 {%0,%1,%2,%3}, [%4];" \
        : "=r"((r)[0]), "=r"((r)[1]), "=r"((r)[2]), "=r"((r)[3]) : "r"(addr))
#define LDSM_X2(r, addr) \
    asm volatile("ldmatrix.sync.aligned.m8n8.x2.shared.b16 {%0,%1}, [%2];" \
        : "=r"((r)[0]), "=r"((r)[1]) : "r"(addr))
#define LDSM_X2T(r, addr) \
    asm volatile("ldmatrix.sync.aligned.m8n8.x2.trans.shared.b16 {%0,%1}, [%2];" \
        : "=r"((r)[0]), "=r"((r)[1]) : "r"(addr))

__device__ __forceinline__ uint32_t pack_h2(float lo, float hi) {
    __half2 h = __floats2half2_rn(lo, hi);
    return *(uint32_t*)&h;
}

// ---------------------------------------------------------------------------
// Weight pre-cast: fp32 -> fp16
// ---------------------------------------------------------------------------
__global__ __launch_bounds__(256)
void half_cast(const float* __restrict__ s, __half* __restrict__ d, int n4)
{
    const int i = blockIdx.x * 256 + threadIdx.x;
    if (i < n4) {
        const float4 v = ((const float4*)s)[i];
        uint2 o;
        o.x = pack_h2(v.x, v.y);
        o.y = pack_h2(v.z, v.w);
        ((uint2*)d)[i] = o;
    }
}

// ---------------------------------------------------------------------------
// fp16 mma.sync GEMM: C[M,N] = A[M,K] @ W[N,K]^T + bias (+gelu / +residual)
//   R14 shape: 128x128 CTA tile, 8 warps (2x4), warp tile 64x32, 256 threads,
//   2 CTA/SM. BK=64, verified XOR swizzle, 3-stage cp.async, 1 sync/k-iter.
//   New: B fragments via paired LDSM.x4 (2 loads cover all 4 n8-tiles).
//   Accumulation order identical to R14 -> bitwise-identical output.
// ---------------------------------------------------------------------------
#define EPI_NONE 0
#define EPI_GELU 1
#define EPI_RES  2

#define GBK       64
#define GSTAGES   3
#define ABLK_B    (128 * 128)                 // 16384 bytes (128 rows x 128B)
#define STAGE_B   (2 * ABLK_B)                // 32768
#define DSMEM_SZ  (GSTAGES * STAGE_B)         // 98304 bytes

template<int EPI, bool OH>
__global__ __launch_bounds__(256, 2)
void gemm_mma(const __half* __restrict__ A, const __half* __restrict__ W,
              const float* __restrict__ bias, const float* __restrict__ Res,
              void* __restrict__ Cv, int N, int K)
{
    extern __shared__ char smc[];
    const uint32_t smA = smem_u32(smc);

    const int tid  = threadIdx.x;
    const int bm   = blockIdx.y * 128;
    const int bn   = blockIdx.x * 128;
    const int warp = tid >> 5, lane = tid & 31;
    const int wm   = (warp >> 2) * 64;        // 0,64
    const int wn   = (warp & 3) * 32;         // 0,32,64,96
    const int qr   = lane >> 2;               // 0..7
    const int qc   = lane & 3;                // 0..3
    const int lx   = lane & 7;

    // per-lane ldmatrix row bases (bytes, stage-relative); rows are 128B
    const uint32_t aRow = (uint32_t)(wm + (lane & 15)) << 7;
    const uint32_t aBit = (uint32_t)(lane >> 4);
    // B x4 pairing: lanes 16-31 address rows +8 (second n8-tile of the pair);
    // (wn + 8g + lx) & 7 == lx, so the swizzle XOR term stays ^lx.
    const uint32_t bRow = (uint32_t)(wn + ((lane >> 4) << 3) + lx) << 7;
    const uint32_t bBit = (uint32_t)((lane >> 3) & 1);

    float acc[4][4][4];
    #pragma unroll
    for (int i = 0; i < 4; i++)
        #pragma unroll
        for (int j = 0; j < 4; j++)
            #pragma unroll
            for (int k = 0; k < 4; k++) acc[i][j][k] = 0.f;

    // cp.async: thread -> row tid>>1, chunk base (tid&1)*4, 4 x 16B (=8 fp16)
    const int  lrow = tid >> 1;
    const int  cb   = (tid & 1) * 4;
    const __half* Ap = A + (long)(bm + lrow) * K;
    const __half* Wp = W + (long)(bn + lrow) * K;
    const uint32_t dA = smA + lrow * 128;
    const uint32_t dB = smA + ABLK_B + lrow * 128;
    const int rx = lrow & 7;

    const int T = K / GBK;

    // prologue: stages 0,1
    #pragma unroll
    for (int u = 0; u < 2; ++u) {
        const uint32_t sb = u * STAGE_B;
        #pragma unroll
        for (int j = 0; j < 4; j++) {
            const int c = cb + j;
            const uint32_t so = ((c ^ rx) << 4);
            cp_async16(dA + sb + so, Ap + (long)u * GBK + c * 8);
            cp_async16(dB + sb + so, Wp + (long)u * GBK + c * 8);
        }
        CP_COMMIT();
    }

    for (int t = 0; t < T; ++t) {
        CP_WAIT(1);
        __syncthreads();                      // all warps done reading stage (t-1)%3

        if (t + 2 < T) {
            const int u = t + 2;
            const uint32_t sb = (u % GSTAGES) * STAGE_B;
            #pragma unroll
            for (int j = 0; j < 4; j++) {
                const int c = cb + j;
                const uint32_t so = ((c ^ rx) << 4);
                cp_async16(dA + sb + so, Ap + (long)u * GBK + c * 8);
                cp_async16(dB + sb + so, Wp + (long)u * GBK + c * 8);
            }
        }
        CP_COMMIT();

        const uint32_t stb = smA + (t % GSTAGES) * STAGE_B;

        #pragma unroll
        for (int ks = 0; ks < 4; ++ks) {      // 4 x k16 = 64 K per iter
            uint32_t a[4][4], b4[2][4];
            const uint32_t aAddr = stb + aRow
                                 + ((((uint32_t)(ks << 1) + aBit) ^ ((aRow >> 7) & 7u)) << 4);
            const uint32_t bAddr = stb + ABLK_B + bRow
                                 + ((((uint32_t)(ks << 1) + bBit) ^ (uint32_t)lx) << 4);
            #pragma unroll
            for (int mt = 0; mt < 4; ++mt)
                LDSM_X4(a[mt], aAddr + mt * 2048);
            #pragma unroll
            for (int j = 0; j < 2; ++j)
                LDSM_X4(b4[j], bAddr + j * 2048);      // 16 rows per load
            #pragma unroll
            for (int mt = 0; mt < 4; ++mt)
                #pragma unroll
                for (int nt = 0; nt < 4; ++nt)
                    MMA_F16(acc[mt][nt], a[mt],
                            b4[nt >> 1][(nt & 1) * 2],
                            b4[nt >> 1][(nt & 1) * 2 + 1]);
        }
    }

    // epilogue (acc fp32; OH -> fp16 output, else fp32)
    #pragma unroll
    for (int mt = 0; mt < 4; ++mt) {
        #pragma unroll
        for (int r2 = 0; r2 < 2; ++r2) {
            const long row = bm + wm + mt * 16 + qr + r2 * 8;
            const float* Rrow = (EPI == EPI_RES) ? (Res + row * (long)N + bn)
                                                 : (const float*)nullptr;
            #pragma unroll
            for (int nt = 0; nt < 4; ++nt) {
                const int col = wn + nt * 8 + qc * 2;
                float vx = acc[mt][nt][r2 * 2 + 0];
                float vy = acc[mt][nt][r2 * 2 + 1];
                const float2 bv = *(const float2*)(bias + bn + col);
                vx += bv.x; vy += bv.y;
                if (EPI == EPI_GELU) {
                    vx = 0.5f * vx * (1.0f + erff(vx * 0.7071067811865475f));
                    vy = 0.5f * vy * (1.0f + erff(vy * 0.7071067811865475f));
                }
                if (EPI == EPI_RES) {
                    const float2 rv = *(const float2*)(Rrow + col);
                    vx += rv.x; vy += rv.y;
                }
                if (OH) {
                    __half* Crow = (__half*)Cv + row * (long)N + bn;
                    *(uint32_t*)(Crow + col) = pack_h2(vx, vy);
                } else {
                    float* Crow = (float*)Cv + row * (long)N + bn;
                    float2 o; o.x = vx; o.y = vy;
                    *(float2*)(Crow + col) = o;
                }
            }
        }
    }
}

// ---------------------------------------------------------------------------
// LayerNorm: fp32 in, fp16 out (consumed only as GEMM A operand)
// ---------------------------------------------------------------------------
__global__ __launch_bounds__(256)
void ln_kernel(const float* __restrict__ x, const float* __restrict__ w,
               const float* __restrict__ b, __half* __restrict__ y)
{
    const long row = blockIdx.x;
    const float4* xr = (const float4*)(x + (row << 10));
    float4 xv = xr[threadIdx.x];

    float s  = xv.x + xv.y + xv.z + xv.w;
    float sq = xv.x * xv.x + xv.y * xv.y + xv.z * xv.z + xv.w * xv.w;
    #pragma unroll
    for (int o = 16; o; o >>= 1) {
        s  += __shfl_xor_sync(0xffffffffu, s,  o);
        sq += __shfl_xor_sync(0xffffffffu, sq, o);
    }
    __shared__ float ss[8], ssq[8];
    __shared__ float mu_s, rstd_s;
    const int warp = threadIdx.x >> 5, lane = threadIdx.x & 31;
    if (lane == 0) { ss[warp] = s; ssq[warp] = sq; }
    __syncthreads();
    if (threadIdx.x == 0) {
        float S = 0.f, SQ = 0.f;
        #pragma unroll
        for (int i = 0; i < 8; i++) { S += ss[i]; SQ += ssq[i]; }
        const float mu  = S * (1.0f / 1024.0f);
        const float var = SQ * (1.0f / 1024.0f) - mu * mu;
        mu_s   = mu;
        rstd_s = rsqrtf(var + 1e-6f);
    }
    __syncthreads();
    const float mu = mu_s, rstd = rstd_s;

    const float4 wv = ((const float4*)w)[threadIdx.x];
    const float4 bv = ((const float4*)b)[threadIdx.x];
    uint2 o;
    o.x = pack_h2((xv.x - mu) * rstd * wv.x + bv.x,
                  (xv.y - mu) * rstd * wv.y + bv.y);
    o.y = pack_h2((xv.z - mu) * rstd * wv.z + bv.z,
                  (xv.w - mu) * rstd * wv.w + bv.w);
    ((uint2*)(y + (row << 10)))[threadIdx.x] = o;
}

// ---------------------------------------------------------------------------
// Flash attention, fp16 mma.sync m16n8k16 (R14 version).
//   Q-tile 128 (256 threads, 8 warps). K via LDSM.x2, P via LDSM.x4,
//   V via LDSM.x2.trans. fp32 accumulators + softmax.
//   Row strides: Q/K/V 144B, P 80B (all multiples of 16B).
// ---------------------------------------------------------------------------
#define QROWS   128
#define AQ_B    144
#define AK_B    144
#define AV_B    144
#define AP_B    80
#define OFF_Q   0
#define OFF_K   (QROWS * AQ_B)                         // 18432
#define OFF_V   (OFF_K + 2 * 32 * AK_B)                // 27648
#define OFF_P   (OFF_V + 2 * 32 * AV_B)                // 36864
#define ATTN_SMEM (OFF_P + QROWS * AP_B)               // 47104 B

__global__ __launch_bounds__(256, 2)
void attn_mma(const __half* __restrict__ qkv, __half* __restrict__ out)
{
    extern __shared__ char asmc[];
    const uint32_t smb = smem_u32(asmc);
    const uint32_t sQ = smb + OFF_Q, sK = smb + OFF_K;
    const uint32_t sV = smb + OFF_V, sP = smb + OFF_P;

    const int tid  = threadIdx.x;
    const int warp = tid >> 5, lane = tid & 31;
    const int qr   = lane >> 2, qc = lane & 3;
    const int lx   = lane & 7;
    const int b    = blockIdx.y >> 4, h = blockIdx.y & 15;
    const int q0   = blockIdx.x * QROWS;
    const int wm   = warp * 16;               // 0..112
    const long base = (long)b * SS * 3072 + h * 64;

    // Q tile (128 rows x 8 chunks = 1024): 4 per thread
    #pragma unroll
    for (int i = 0; i < 4; i++) {
        const int cc = tid + i * 256;
        const int row = cc >> 3, c = cc & 7;
        cp_async16(sQ + row * AQ_B + c * 16,
                   qkv + base + (long)(q0 + row) * 3072 + c * 8);
    }
    // K/V tile kt=0 (32 rows x 8 chunks = 256 each): 1 per thread each
    {
        const int row = tid >> 3, c = tid & 7;
        const long ko = base + 1024 + (long)row * 3072 + c * 8;
        cp_async16(sK + row * AK_B + c * 16, qkv + ko);
        cp_async16(sV + row * AV_B + c * 16, qkv + ko + 1024);
    }
    CP_COMMIT();
    CP_WAIT(0);
    __syncthreads();

    // Q fragments: scale by 0.125 (exact in fp16), register-resident.
    uint32_t qa[4][4];
    {
        const int r0off = OFF_Q + (wm + qr) * AQ_B + qc * 4;
        const int r1off = r0off + 8 * AQ_B;
        const __half2 s8 = __floats2half2_rn(0.125f, 0.125f);
        #pragma unroll
        for (int ks = 0; ks < 4; ks++) {
            __half2 a0 = __hmul2(*(const __half2*)(asmc + r0off + ks * 32), s8);
            __half2 a1 = __hmul2(*(const __half2*)(asmc + r1off + ks * 32), s8);
            __half2 a2 = __hmul2(*(const __half2*)(asmc + r0off + ks * 32 + 16), s8);
            __half2 a3 = __hmul2(*(const __half2*)(asmc + r1off + ks * 32 + 16), s8);
            qa[ks][0] = *(uint32_t*)&a0;
            qa[ks][1] = *(uint32_t*)&a1;
            qa[ks][2] = *(uint32_t*)&a2;
            qa[ks][3] = *(uint32_t*)&a3;
        }
    }

    const uint32_t kBit = (uint32_t)((lane >> 3) & 1);

    float o[8][4];
    #pragma unroll
    for (int nt = 0; nt < 8; nt++)
        #pragma unroll
        for (int k = 0; k < 4; k++) o[nt][k] = 0.f;
    float mrow0 = -1e30f, mrow1 = -1e30f, l0 = 0.f, l1 = 0.f;

    for (int kt = 0; kt < 32; kt++) {
        const int cur = kt & 1;
        CP_WAIT(0);
        __syncthreads();
        if (kt + 1 < 32) {
            const int nxt = cur ^ 1;
            const int row = tid >> 3, c = tid & 7;
            const long ko = base + 1024
                          + (long)((kt + 1) * 32 + row) * 3072 + c * 8;
            cp_async16(sK + (nxt * 32 + row) * AK_B + c * 16, qkv + ko);
            cp_async16(sV + (nxt * 32 + row) * AV_B + c * 16, qkv + ko + 1024);
        }
        CP_COMMIT();

        const uint32_t sKc = sK + cur * 32 * AK_B;
        const uint32_t sVc = sV + cur * 32 * AV_B;

        // S = (Q/8) K^T : 4 k16-steps, K frags LDSM.x2
        float s[4][4];
        #pragma unroll
        for (int nt = 0; nt < 4; nt++)
            #pragma unroll
            for (int k = 0; k < 4; k++) s[nt][k] = 0.f;
        #pragma unroll
        for (int ks = 0; ks < 4; ks++) {
            const uint32_t kAddr = sKc + (uint32_t)lx * AK_B
                                 + (((uint32_t)(ks << 1) + kBit) << 4);
            uint32_t bf[4][2];
            #pragma unroll
            for (int nt = 0; nt < 4; nt++)
                LDSM_X2(bf[nt], kAddr + nt * (8 * AK_B));
            #pragma unroll
            for (int nt = 0; nt < 4; nt++)
                MMA_F16(s[nt], qa[ks], bf[nt][0], bf[nt][1]);
        }

        // online softmax
        float m0 = -1e30f, m1 = -1e30f;
        #pragma unroll
        for (int nt = 0; nt < 4; nt++) {
            m0 = fmaxf(m0, fmaxf(s[nt][0], s[nt][1]));
            m1 = fmaxf(m1, fmaxf(s[nt][2], s[nt][3]));
        }
        m0 = fmaxf(m0, __shfl_xor_sync(0xffffffffu, m0, 1));
        m0 = fmaxf(m0, __shfl_xor_sync(0xffffffffu, m0, 2));
        m1 = fmaxf(m1, __shfl_xor_sync(0xffffffffu, m1, 1));
        m1 = fmaxf(m1, __shfl_xor_sync(0xffffffffu, m1, 2));
        const float n0 = fmaxf(mrow0, m0), n1 = fmaxf(mrow1, m1);
        const float c0 = __expf(mrow0 - n0), c1 = __expf(mrow1 - n1);
        float ps0 = 0.f, ps1 = 0.f;
        char* P0 = asmc + (OFF_P + (wm + qr) * AP_B + qc * 4);
        char* P1 = P0 + 8 * AP_B;
        #pragma unroll
        for (int nt = 0; nt < 4; nt++) {
            const float p00 = __expf(s[nt][0] - n0);
            const float p01 = __expf(s[nt][1] - n0);
            const float p10 = __expf(s[nt][2] - n1);
            const float p11 = __expf(s[nt][3] - n1);
            ps0 += p00 + p01;
            ps1 += p10 + p11;
            *(uint32_t*)(P0 + nt * 16) = pack_h2(p00, p01);
            *(uint32_t*)(P1 + nt * 16) = pack_h2(p10, p11);
        }
        ps0 += __shfl_xor_sync(0xffffffffu, ps0, 1);
        ps0 += __shfl_xor_sync(0xffffffffu, ps0, 2);
        ps1 += __shfl_xor_sync(0xffffffffu, ps1, 1);
        ps1 += __shfl_xor_sync(0xffffffffu, ps1, 2);
        l0 = l0 * c0 + ps0;
        l1 = l1 * c1 + ps1;
        mrow0 = n0; mrow1 = n1;
        #pragma unroll
        for (int nt = 0; nt < 8; nt++) {
            o[nt][0] *= c0; o[nt][1] *= c0;
            o[nt][2] *= c1; o[nt][3] *= c1;
        }
        __syncwarp();

        // O += P V : 2 k16-steps; P LDSM.x4, V LDSM.x2.trans
        #pragma unroll
        for (int ks2 = 0; ks2 < 2; ks2++) {
            uint32_t pa[4];
            const uint32_t pAddr = sP + (uint32_t)(wm + (lane & 15)) * AP_B
                                 + (((uint32_t)(ks2 << 1) + (uint32_t)(lane >> 4)) << 4);
            LDSM_X4(pa, pAddr);
            const uint32_t vRow = sVc
                + (uint32_t)(ks2 * 16 + (lane & 7) + ((lane >> 3) & 1) * 8) * AV_B;
            #pragma unroll
            for (int nt = 0; nt < 8; nt++) {
                uint32_t bv[2];
                LDSM_X2T(bv, vRow + (nt << 4));
                MMA_F16(o[nt], pa, bv[0], bv[1]);
            }
        }
        __syncwarp();
    }

    const float i0 = 1.0f / l0, i1 = 1.0f / l1;
    const long r0g = (long)(b * SS + q0 + wm + qr);
    __half* d0 = out + r0g * EE + h * 64 + 2 * qc;
    __half* d1 = d0 + 8 * EE;
    #pragma unroll
    for (int nt = 0; nt < 8; nt++) {
        *(uint32_t*)(d0 + nt * 8) = pack_h2(o[nt][0] * i0, o[nt][1] * i0);
        *(uint32_t*)(d1 + nt * 8) = pack_h2(o[nt][2] * i1, o[nt][3] * i1);
    }
}

// ---------------------------------------------------------------------------
// Launch sequence
// ---------------------------------------------------------------------------
extern "C" void kernel_launch(void* const* d_in, const int* in_sizes, int n_in,
                              void* d_out, int out_size)
{
    const float* x         = (const float*)d_in[0];
    const float* ln1_w     = (const float*)d_in[1];
    const float* ln1_b     = (const float*)d_in[2];
    const float* ln2_w     = (const float*)d_in[3];
    const float* ln2_b     = (const float*)d_in[4];
    const float* in_proj_w = (const float*)d_in[5];
    const float* in_proj_b = (const float*)d_in[6];
    const float* out_w     = (const float*)d_in[7];
    const float* out_b     = (const float*)d_in[8];
    const float* w1        = (const float*)d_in[9];
    const float* b1        = (const float*)d_in[10];
    const float* w2        = (const float*)d_in[11];
    const float* b2        = (const float*)d_in[12];
    float* outp            = (float*)d_out;

    __half *h, *qkv, *attn, *ffn, *wq, *wo, *w1t, *w2t;
    float  *x2;
    cudaGetSymbolAddress((void**)&h,    g_h);
    cudaGetSymbolAddress((void**)&qkv,  g_qkv);
    cudaGetSymbolAddress((void**)&attn, g_attn);
    cudaGetSymbolAddress((void**)&x2,   g_x2);
    cudaGetSymbolAddress((void**)&ffn,  g_ffn);
    cudaGetSymbolAddress((void**)&wq,   g_wq);
    cudaGetSymbolAddress((void**)&wo,   g_wo);
    cudaGetSymbolAddress((void**)&w1t,  g_w1);
    cudaGetSymbolAddress((void**)&w2t,  g_w2);

    cudaFuncSetAttribute(gemm_mma<EPI_NONE, true>,  cudaFuncAttributeMaxDynamicSharedMemorySize, DSMEM_SZ);
    cudaFuncSetAttribute(gemm_mma<EPI_GELU, true>,  cudaFuncAttributeMaxDynamicSharedMemorySize, DSMEM_SZ);
    cudaFuncSetAttribute(gemm_mma<EPI_RES,  false>, cudaFuncAttributeMaxDynamicSharedMemorySize, DSMEM_SZ);
    cudaFuncSetAttribute(attn_mma, cudaFuncAttributeMaxDynamicSharedMemorySize, ATTN_SMEM);

    // 0. pre-cast weights to fp16 (HBM-bound, ~25us total)
    half_cast<<<(3 * EE * EE / 4 + 255) / 256, 256>>>(in_proj_w, wq, 3 * EE * EE / 4);
    half_cast<<<(EE * EE / 4 + 255) / 256, 256>>>(out_w, wo, EE * EE / 4);
    half_cast<<<(FFN * EE / 4 + 255) / 256, 256>>>(w1, w1t, FFN * EE / 4);
    half_cast<<<(EE * FFN / 4 + 255) / 256, 256>>>(w2, w2t, EE * FFN / 4);

    // 1. h = fp16(LN1(x))
    ln_kernel<<<MM, 256>>>(x, ln1_w, ln1_b, h);
    // 2. qkv = fp16(h @ wq^T + b)                     [16384, 3072]
    gemm_mma<EPI_NONE, true><<<dim3(3 * EE / 128, MM / 128), 256, DSMEM_SZ>>>(
        h, wq, in_proj_b, nullptr, qkv, 3 * EE, EE);
    // 3. attention (fp16 in/out, fp32 softmax+acc)
    attn_mma<<<dim3(SS / QROWS, BB * HH), 256, ATTN_SMEM>>>(qkv, attn);
    // 4. x2 = x + attn @ wo^T + out_b                 (fp32 out)
    gemm_mma<EPI_RES, false><<<dim3(EE / 128, MM / 128), 256, DSMEM_SZ>>>(
        attn, wo, out_b, x, x2, EE, EE);
    // 5. h = fp16(LN2(x2))
    ln_kernel<<<MM, 256>>>(x2, ln2_w, ln2_b, h);
    // 6. ffn = fp16(gelu(h @ w1^T + b1))              [16384, 4096]
    gemm_mma<EPI_GELU, true><<<dim3(FFN / 128, MM / 128), 256, DSMEM_SZ>>>(
        h, w1t, b1, nullptr, ffn, FFN, EE);
    // 7. out = x2 + ffn @ w2^T + b2                   (fp32 out)
    gemm_mma<EPI_RES, false><<<dim3(EE / 128, MM / 128), 256, DSMEM_SZ>>>(
        ffn, w2t, b2, x2, outp, EE, FFN);
}